// round 1
// baseline (speedup 1.0000x reference)
#include <cuda_runtime.h>
#include <cuda_bf16.h>

#define T_DIM 512
#define B_DIM 512
#define FDIM  64
#define H_DIM 128
#define G3    384   // 3*H

// ---- scratch (device globals; no allocation) ----
__device__ float g_xw[(size_t)B_DIM * T_DIM * G3];   // 402 MB: x@Wx + b_in, per (b,t)
__device__ float g_whT[G3 * H_DIM];                  // Wh transposed: [col][k]
__device__ float g_hfinal[B_DIM * H_DIM];            // final GRU state

// ---------------------------------------------------------------------------
// Kernel 0: transpose Wh (128 x 384) -> WhT (384 x 128) so scan loads are
// contiguous in k (float4-able).
// ---------------------------------------------------------------------------
__global__ void wh_transpose_kernel(const float* __restrict__ Wh) {
    int col = blockIdx.x;
    for (int k = threadIdx.x; k < H_DIM; k += blockDim.x)
        g_whT[col * H_DIM + k] = Wh[k * G3 + col];
}

// ---------------------------------------------------------------------------
// Kernel 1: xw[b,t,:] = x[b,t,:] @ Wx + b_in
// 8 rows per block, 384 threads (one output column each), Wx value reused
// across the 8 rows -> FMA-bound, Wx stays L1-resident (96 KB).
// ---------------------------------------------------------------------------
__global__ void __launch_bounds__(384) xw_kernel(const float* __restrict__ inputs,
                                                 const float* __restrict__ Wx,
                                                 const float* __restrict__ bias) {
    __shared__ float xsT[FDIM * 8];   // [k][r], r contiguous
    const int row0 = blockIdx.x * 8;
    const int tid  = threadIdx.x;

    for (int i = tid; i < FDIM * 8; i += 384) {
        int k = i >> 3, r = i & 7;
        xsT[k * 8 + r] = inputs[(size_t)(row0 + r) * 65 + k];
    }
    __syncthreads();

    const int j = tid;
    const float bi = bias[j];                 // b_in = b[0][j]
    float acc[8];
    #pragma unroll
    for (int r = 0; r < 8; r++) acc[r] = bi;

    #pragma unroll 8
    for (int k = 0; k < FDIM; k++) {
        float w = __ldg(&Wx[k * G3 + j]);
        float4 xa = *reinterpret_cast<const float4*>(&xsT[k * 8]);
        float4 xb = *reinterpret_cast<const float4*>(&xsT[k * 8 + 4]);
        acc[0] = fmaf(w, xa.x, acc[0]);
        acc[1] = fmaf(w, xa.y, acc[1]);
        acc[2] = fmaf(w, xa.z, acc[2]);
        acc[3] = fmaf(w, xa.w, acc[3]);
        acc[4] = fmaf(w, xb.x, acc[4]);
        acc[5] = fmaf(w, xb.y, acc[5]);
        acc[6] = fmaf(w, xb.z, acc[6]);
        acc[7] = fmaf(w, xb.w, acc[7]);
    }
    #pragma unroll
    for (int r = 0; r < 8; r++)
        g_xw[(size_t)(row0 + r) * G3 + j] = acc[r];
}

// ---------------------------------------------------------------------------
// Kernel 2: GRU scan. 128 blocks x 384 threads; block owns 4 batches.
// Thread t = (gate g = t>>7, unit j = t&127), computes rec column t for its
// 4 batches (4 accumulators). WhT streamed from global (L1-resident 196 KB),
// h lives in smem, gate values exchanged through smem each step.
// ---------------------------------------------------------------------------
__device__ __forceinline__ float fsigmoid(float x) {
    return __fdividef(1.f, 1.f + __expf(-x));
}
__device__ __forceinline__ float ftanh(float x) {
    float e = __expf(2.f * x);
    return 1.f - __fdividef(2.f, e + 1.f);
}

__global__ void __launch_bounds__(384) gru_scan_kernel(const float* __restrict__ bias) {
    __shared__ float  hs[4][H_DIM];     // current h, [batch][unit]
    __shared__ float4 gez[H_DIM];       // z preact (xz+rz+b)
    __shared__ float4 ger[H_DIM];       // r preact
    __shared__ float4 geh[H_DIM];       // rh (recurrent part + b_rec)
    __shared__ float4 gxh[H_DIM];       // xh (input part)

    const int t  = threadIdx.x;
    const int b0 = blockIdx.x * 4;
    const int g  = t >> 7;
    const int j  = t & 127;

    for (int i = t; i < 4 * H_DIM; i += 384) (&hs[0][0])[i] = 0.f;
    const float brec = bias[G3 + t];    // b_rec[t]
    const float* __restrict__ wp = &g_whT[t * H_DIM];
    __syncthreads();

    for (int step = 0; step < T_DIM; step++) {
        // input-path values for this step (issued early, hidden under k-loop)
        float xv0 = g_xw[((size_t)(b0 + 0) * T_DIM + step) * G3 + t];
        float xv1 = g_xw[((size_t)(b0 + 1) * T_DIM + step) * G3 + t];
        float xv2 = g_xw[((size_t)(b0 + 2) * T_DIM + step) * G3 + t];
        float xv3 = g_xw[((size_t)(b0 + 3) * T_DIM + step) * G3 + t];

        float a0 = 0.f, a1 = 0.f, a2 = 0.f, a3 = 0.f;
        #pragma unroll 8
        for (int k4 = 0; k4 < H_DIM / 4; k4++) {
            float4 w  = __ldg(reinterpret_cast<const float4*>(wp + k4 * 4));
            float4 h0 = *reinterpret_cast<const float4*>(&hs[0][k4 * 4]);
            float4 h1 = *reinterpret_cast<const float4*>(&hs[1][k4 * 4]);
            float4 h2 = *reinterpret_cast<const float4*>(&hs[2][k4 * 4]);
            float4 h3 = *reinterpret_cast<const float4*>(&hs[3][k4 * 4]);
            a0 = fmaf(w.x, h0.x, a0); a0 = fmaf(w.y, h0.y, a0);
            a0 = fmaf(w.z, h0.z, a0); a0 = fmaf(w.w, h0.w, a0);
            a1 = fmaf(w.x, h1.x, a1); a1 = fmaf(w.y, h1.y, a1);
            a1 = fmaf(w.z, h1.z, a1); a1 = fmaf(w.w, h1.w, a1);
            a2 = fmaf(w.x, h2.x, a2); a2 = fmaf(w.y, h2.y, a2);
            a2 = fmaf(w.z, h2.z, a2); a2 = fmaf(w.w, h2.w, a2);
            a3 = fmaf(w.x, h3.x, a3); a3 = fmaf(w.y, h3.y, a3);
            a3 = fmaf(w.z, h3.z, a3); a3 = fmaf(w.w, h3.w, a3);
        }

        float4 v;
        if (g == 0) {
            v.x = a0 + brec + xv0; v.y = a1 + brec + xv1;
            v.z = a2 + brec + xv2; v.w = a3 + brec + xv3;
            gez[j] = v;
        } else if (g == 1) {
            v.x = a0 + brec + xv0; v.y = a1 + brec + xv1;
            v.z = a2 + brec + xv2; v.w = a3 + brec + xv3;
            ger[j] = v;
        } else {
            v.x = a0 + brec; v.y = a1 + brec; v.z = a2 + brec; v.w = a3 + brec;
            geh[j] = v;
            float4 u; u.x = xv0; u.y = xv1; u.z = xv2; u.w = xv3;
            gxh[j] = u;
        }
        __syncthreads();

        if (t < H_DIM) {
            float4 zp = gez[j];
            float4 rp = ger[j];
            float4 hp = geh[j];
            float4 xh = gxh[j];
            {
                float z = fsigmoid(zp.x), r = fsigmoid(rp.x);
                float hh = ftanh(xh.x + r * hp.x);
                hs[0][j] = z * hs[0][j] + (1.f - z) * hh;
            }
            {
                float z = fsigmoid(zp.y), r = fsigmoid(rp.y);
                float hh = ftanh(xh.y + r * hp.y);
                hs[1][j] = z * hs[1][j] + (1.f - z) * hh;
            }
            {
                float z = fsigmoid(zp.z), r = fsigmoid(rp.z);
                float hh = ftanh(xh.z + r * hp.z);
                hs[2][j] = z * hs[2][j] + (1.f - z) * hh;
            }
            {
                float z = fsigmoid(zp.w), r = fsigmoid(rp.w);
                float hh = ftanh(xh.w + r * hp.w);
                hs[3][j] = z * hs[3][j] + (1.f - z) * hh;
            }
        }
        __syncthreads();
    }

    if (t < H_DIM) {
        #pragma unroll
        for (int bb = 0; bb < 4; bb++)
            g_hfinal[(size_t)(b0 + bb) * H_DIM + j] = hs[bb][j];
    }
}

// ---------------------------------------------------------------------------
// Kernel 3: head. hidden += W_state[idx]; h1 = BN(relu(hidden@w1+b1)); out=h1@w2+b2
// ---------------------------------------------------------------------------
__global__ void head_kernel(const float* __restrict__ inputs,
                            const float* __restrict__ W_state,
                            const float* __restrict__ w1,
                            const float* __restrict__ b1,
                            const float* __restrict__ gamma,
                            const float* __restrict__ beta,
                            const float* __restrict__ mean,
                            const float* __restrict__ var,
                            const float* __restrict__ w2,
                            const float* __restrict__ b2,
                            float* __restrict__ out) {
    const int b = blockIdx.x;
    const int t = threadIdx.x;   // 128 threads
    __shared__ float hid[H_DIM];
    __shared__ float red[64];

    if (t < H_DIM) {
        float st = inputs[((size_t)b * T_DIM + (T_DIM - 1)) * 65 + 64];
        int idx = (int)st;
        idx = idx < 0 ? 0 : (idx > 2 ? 2 : idx);
        hid[t] = g_hfinal[(size_t)b * H_DIM + t] + W_state[idx * H_DIM + t];
    }
    __syncthreads();

    if (t < 64) {
        float a = b1[t];
        #pragma unroll 8
        for (int k = 0; k < H_DIM; k++)
            a = fmaf(hid[k], w1[k * 64 + t], a);
        a = fmaxf(a, 0.f);
        a = (a - mean[t]) * rsqrtf(var[t] + 1e-3f) * gamma[t] + beta[t];
        red[t] = a * w2[t];
    }
    __syncthreads();

    if (t == 0) {
        float s = b2[0];
        #pragma unroll 8
        for (int k = 0; k < 64; k++) s += red[k];
        out[b] = s;
    }
}

// ---------------------------------------------------------------------------
extern "C" void kernel_launch(void* const* d_in, const int* in_sizes, int n_in,
                              void* d_out, int out_size) {
    const float* inputs  = (const float*)d_in[0];
    const float* Wx      = (const float*)d_in[1];
    const float* Wh      = (const float*)d_in[2];
    const float* bias    = (const float*)d_in[3];
    const float* W_state = (const float*)d_in[4];
    const float* w1      = (const float*)d_in[5];
    const float* b1      = (const float*)d_in[6];
    const float* gamma   = (const float*)d_in[7];
    const float* beta    = (const float*)d_in[8];
    const float* mean    = (const float*)d_in[9];
    const float* var     = (const float*)d_in[10];
    const float* w2      = (const float*)d_in[11];
    const float* b2      = (const float*)d_in[12];
    float* out = (float*)d_out;

    wh_transpose_kernel<<<G3, 128>>>(Wh);
    xw_kernel<<<(B_DIM * T_DIM) / 8, 384>>>(inputs, Wx, bias);
    gru_scan_kernel<<<B_DIM / 4, 384>>>(bias);
    head_kernel<<<B_DIM, 128>>>(inputs, W_state, w1, b1, gamma, beta,
                                mean, var, w2, b2, out);
}

// round 2
// speedup vs baseline: 2.1428x; 2.1428x over previous
#include <cuda_runtime.h>
#include <cuda_bf16.h>

#define T_DIM 512
#define B_DIM 512
#define FDIM  64
#define H_DIM 128
#define G3    384   // 3*H
#define BSTRIDE ((size_t)T_DIM * G3)

// ---- scratch (device globals; no allocation) ----
__device__ float g_xw[(size_t)B_DIM * T_DIM * G3];   // x@Wx + b_in per (b,t)
__device__ float g_whT[G3 * H_DIM];                  // Wh^T: [col][k], k contiguous
__device__ float g_wxT[G3 * FDIM];                   // Wx^T: [col][k], k contiguous
__device__ float g_hfinal[B_DIM * H_DIM];            // final GRU state

// packed f32x2 fused multiply-add: d = a*b + d (per 32-bit lane)
__device__ __forceinline__ void ffma2(unsigned long long& d,
                                      unsigned long long a,
                                      unsigned long long b) {
    asm("fma.rn.f32x2 %0, %1, %2, %3;" : "=l"(d) : "l"(a), "l"(b), "l"(d));
}
__device__ __forceinline__ float ull_hsum(unsigned long long u) {
    float lo, hi;
    asm("mov.b64 {%0,%1}, %2;" : "=f"(lo), "=f"(hi) : "l"(u));
    return lo + hi;
}
__device__ __forceinline__ float fsigmoid(float x) {
    return __fdividef(1.f, 1.f + __expf(-x));
}
__device__ __forceinline__ float ftanh(float x) {
    float e = __expf(2.f * x);
    return 1.f - __fdividef(2.f, e + 1.f);
}

// ---------------------------------------------------------------------------
// Kernel 0: transpose Wh (128x384) -> WhT[col][k], Wx (64x384) -> WxT[col][k]
// ---------------------------------------------------------------------------
__global__ void transpose_kernel(const float* __restrict__ Wh,
                                 const float* __restrict__ Wx) {
    int c = blockIdx.x;               // 384 blocks
    int k = threadIdx.x;              // 128 threads
    g_whT[c * H_DIM + k] = Wh[k * G3 + c];
    if (k < FDIM)
        g_wxT[c * FDIM + k] = Wx[k * G3 + c];
}

// ---------------------------------------------------------------------------
// Kernel 1: xw[row,:] = x[row,:] @ Wx + b_in, 8 rows/block, 384 threads.
// WxT k-contiguous -> f32x2 k-pair FMAs, x rows broadcast from smem.
// ---------------------------------------------------------------------------
__global__ void __launch_bounds__(384) xw_kernel(const float* __restrict__ inputs,
                                                 const float* __restrict__ bias) {
    __shared__ __align__(16) float xs[8][FDIM];
    const int row0 = blockIdx.x * 8;
    const int tid  = threadIdx.x;

    for (int i = tid; i < 8 * FDIM; i += 384) {
        int r = i >> 6, k = i & 63;
        xs[r][k] = inputs[(size_t)(row0 + r) * 65 + k];
    }
    __syncthreads();

    const int j = tid;
    const ulonglong2* __restrict__ wt =
        reinterpret_cast<const ulonglong2*>(&g_wxT[j * FDIM]);

    unsigned long long acc[8];
    #pragma unroll
    for (int r = 0; r < 8; r++) acc[r] = 0ull;

    #pragma unroll
    for (int k4 = 0; k4 < FDIM / 4; k4++) {
        ulonglong2 w = wt[k4];
        #pragma unroll
        for (int r = 0; r < 8; r++) {
            ulonglong2 x = *reinterpret_cast<const ulonglong2*>(&xs[r][k4 * 4]);
            ffma2(acc[r], w.x, x.x);
            ffma2(acc[r], w.y, x.y);
        }
    }
    const float bi = bias[j];
    #pragma unroll
    for (int r = 0; r < 8; r++)
        g_xw[(size_t)(row0 + r) * G3 + j] = ull_hsum(acc[r]) + bi;
}

// ---------------------------------------------------------------------------
// Kernel 2: GRU scan. 128 blocks x 384 threads, 4 batches/block.
// Thread t owns output column t; its 128 Wh weights live in REGISTERS
// (128 regs/thread, 1 CTA/SM). Recurrent GEMV via f32x2 k-pair FMAs against
// h broadcast from smem. Gates exchanged through conflict-free smem layouts.
// ---------------------------------------------------------------------------
__global__ void __launch_bounds__(384, 1) gru_scan_kernel(const float* __restrict__ bias) {
    __shared__ __align__(16) float hs[4][H_DIM];    // h, batch-major
    __shared__ float ge[4][G3];                     // recurrent preact + b_rec
    __shared__ float xvs[4][G3];                    // input preact (x@Wx + b_in)

    const int t  = threadIdx.x;
    const int b0 = blockIdx.x * 4;

    // Wh column -> registers (64 packed f32x2 values)
    unsigned long long wk[64];
    {
        const ulonglong2* __restrict__ wp =
            reinterpret_cast<const ulonglong2*>(&g_whT[t * H_DIM]);
        #pragma unroll
        for (int i = 0; i < 32; i++) {
            ulonglong2 v = wp[i];
            wk[2 * i]     = v.x;
            wk[2 * i + 1] = v.y;
        }
    }

    for (int i = t; i < 4 * H_DIM; i += 384) (&hs[0][0])[i] = 0.f;
    const float brec = bias[G3 + t];
    const float* __restrict__ xwp = g_xw + (size_t)b0 * BSTRIDE + t;
    __syncthreads();

    for (int step = 0; step < T_DIM; step++) {
        const size_t so = (size_t)step * G3;
        float xv0 = xwp[0 * BSTRIDE + so];
        float xv1 = xwp[1 * BSTRIDE + so];
        float xv2 = xwp[2 * BSTRIDE + so];
        float xv3 = xwp[3 * BSTRIDE + so];

        unsigned long long a0 = 0ull, a1 = 0ull, a2 = 0ull, a3 = 0ull;
        #pragma unroll
        for (int k4 = 0; k4 < H_DIM / 4; k4++) {
            ulonglong2 h0 = *reinterpret_cast<const ulonglong2*>(&hs[0][k4 * 4]);
            ffma2(a0, wk[2 * k4], h0.x);
            ffma2(a0, wk[2 * k4 + 1], h0.y);
            ulonglong2 h1 = *reinterpret_cast<const ulonglong2*>(&hs[1][k4 * 4]);
            ffma2(a1, wk[2 * k4], h1.x);
            ffma2(a1, wk[2 * k4 + 1], h1.y);
            ulonglong2 h2 = *reinterpret_cast<const ulonglong2*>(&hs[2][k4 * 4]);
            ffma2(a2, wk[2 * k4], h2.x);
            ffma2(a2, wk[2 * k4 + 1], h2.y);
            ulonglong2 h3 = *reinterpret_cast<const ulonglong2*>(&hs[3][k4 * 4]);
            ffma2(a3, wk[2 * k4], h3.x);
            ffma2(a3, wk[2 * k4 + 1], h3.y);
        }

        ge[0][t] = ull_hsum(a0) + brec;  xvs[0][t] = xv0;
        ge[1][t] = ull_hsum(a1) + brec;  xvs[1][t] = xv1;
        ge[2][t] = ull_hsum(a2) + brec;  xvs[2][t] = xv2;
        ge[3][t] = ull_hsum(a3) + brec;  xvs[3][t] = xv3;
        __syncthreads();

        // activations: 512 items (b, j) over 384 threads
        for (int i = t; i < 4 * H_DIM; i += 384) {
            int b = i >> 7, j = i & 127;
            float z  = fsigmoid(ge[b][j]       + xvs[b][j]);
            float r  = fsigmoid(ge[b][128 + j] + xvs[b][128 + j]);
            float hh = ftanh(xvs[b][256 + j] + r * ge[b][256 + j]);
            hs[b][j] = z * hs[b][j] + (1.f - z) * hh;
        }
        __syncthreads();
    }

    if (t < 4 * H_DIM - 384) {          // never true (512-384=128): handled below
    }
    if (t < H_DIM) {
        #pragma unroll
        for (int bb = 0; bb < 4; bb++)
            g_hfinal[(size_t)(b0 + bb) * H_DIM + t] = hs[bb][t];
    }
}

// ---------------------------------------------------------------------------
// Kernel 3: head. hidden += W_state[idx]; h1 = BN(relu(hidden@w1+b1)); out=h1@w2+b2
// ---------------------------------------------------------------------------
__global__ void head_kernel(const float* __restrict__ inputs,
                            const float* __restrict__ W_state,
                            const float* __restrict__ w1,
                            const float* __restrict__ b1,
                            const float* __restrict__ gamma,
                            const float* __restrict__ beta,
                            const float* __restrict__ mean,
                            const float* __restrict__ var,
                            const float* __restrict__ w2,
                            const float* __restrict__ b2,
                            float* __restrict__ out) {
    const int b = blockIdx.x;
    const int t = threadIdx.x;   // 128 threads
    __shared__ float hid[H_DIM];
    __shared__ float red[64];

    if (t < H_DIM) {
        float st = inputs[((size_t)b * T_DIM + (T_DIM - 1)) * 65 + 64];
        int idx = (int)st;
        idx = idx < 0 ? 0 : (idx > 2 ? 2 : idx);
        hid[t] = g_hfinal[(size_t)b * H_DIM + t] + W_state[idx * H_DIM + t];
    }
    __syncthreads();

    if (t < 64) {
        float a = b1[t];
        #pragma unroll 8
        for (int k = 0; k < H_DIM; k++)
            a = fmaf(hid[k], w1[k * 64 + t], a);
        a = fmaxf(a, 0.f);
        a = (a - mean[t]) * rsqrtf(var[t] + 1e-3f) * gamma[t] + beta[t];
        red[t] = a * w2[t];
    }
    __syncthreads();

    if (t == 0) {
        float s = b2[0];
        #pragma unroll 8
        for (int k = 0; k < 64; k++) s += red[k];
        out[b] = s;
    }
}

// ---------------------------------------------------------------------------
extern "C" void kernel_launch(void* const* d_in, const int* in_sizes, int n_in,
                              void* d_out, int out_size) {
    const float* inputs  = (const float*)d_in[0];
    const float* Wx      = (const float*)d_in[1];
    const float* Wh      = (const float*)d_in[2];
    const float* bias    = (const float*)d_in[3];
    const float* W_state = (const float*)d_in[4];
    const float* w1      = (const float*)d_in[5];
    const float* b1      = (const float*)d_in[6];
    const float* gamma   = (const float*)d_in[7];
    const float* beta    = (const float*)d_in[8];
    const float* mean    = (const float*)d_in[9];
    const float* var     = (const float*)d_in[10];
    const float* w2      = (const float*)d_in[11];
    const float* b2      = (const float*)d_in[12];
    float* out = (float*)d_out;

    transpose_kernel<<<G3, H_DIM>>>(Wh, Wx);
    xw_kernel<<<(B_DIM * T_DIM) / 8, 384>>>(inputs, bias);
    gru_scan_kernel<<<B_DIM / 4, 384>>>(bias);
    head_kernel<<<B_DIM, 128>>>(inputs, W_state, w1, b1, gamma, beta,
                                mean, var, w2, b2, out);
}

// round 3
// speedup vs baseline: 2.6665x; 1.2444x over previous
#include <cuda_runtime.h>
#include <cuda_bf16.h>

#define T_DIM 512
#define B_DIM 512
#define FDIM  64
#define H_DIM 128
#define G3    384   // 3*H
#define BSTRIDE ((size_t)T_DIM * G3)

// ---- scratch (device globals; no allocation) ----
__device__ float g_xw[(size_t)B_DIM * T_DIM * G3];   // x@Wx + b_in per (b,t)
__device__ float g_whT[G3 * H_DIM];                  // Wh^T: [col][k], k contiguous
__device__ float g_wxT[G3 * FDIM];                   // Wx^T: [col][k], k contiguous
__device__ float g_hfinal[B_DIM * H_DIM];            // final GRU state
__device__ float g_dummy[384];                       // profiling-shift sink

// packed f32x2 fused multiply-add: d = a*b + d (per 32-bit lane)
__device__ __forceinline__ void ffma2(unsigned long long& d,
                                      unsigned long long a,
                                      unsigned long long b) {
    asm("fma.rn.f32x2 %0, %1, %2, %3;" : "=l"(d) : "l"(a), "l"(b), "l"(d));
}
__device__ __forceinline__ float ull_hsum(unsigned long long u) {
    float lo, hi;
    asm("mov.b64 {%0,%1}, %2;" : "=f"(lo), "=f"(hi) : "l"(u));
    return lo + hi;
}
__device__ __forceinline__ float fsigmoid(float x) {
    return __fdividef(1.f, 1.f + __expf(-x));
}
__device__ __forceinline__ float ftanh(float x) {
    float e = __expf(2.f * x);
    return 1.f - __fdividef(2.f, e + 1.f);
}

// ---------------------------------------------------------------------------
// Kernel 0: transpose Wh (128x384) -> WhT[col][k], Wx (64x384) -> WxT[col][k]
// ---------------------------------------------------------------------------
__global__ void transpose_kernel(const float* __restrict__ Wh,
                                 const float* __restrict__ Wx) {
    int c = blockIdx.x;               // 384 blocks
    int k = threadIdx.x;              // 128 threads
    g_whT[c * H_DIM + k] = Wh[k * G3 + c];
    if (k < FDIM)
        g_wxT[c * FDIM + k] = Wx[k * G3 + c];
}

// ---------------------------------------------------------------------------
// Kernel 1: xw[row,:] = x[row,:] @ Wx + b_in.
// 64 rows/block, 384 threads (one output column each). Weight column lives in
// REGISTERS, loaded once per block and reused across 8 row-tiles of 8 ->
// weight wavefront traffic amortized 8x vs round 1; kernel is fma-bound.
// ---------------------------------------------------------------------------
__global__ void __launch_bounds__(384, 1) xw_kernel(const float* __restrict__ inputs,
                                                    const float* __restrict__ bias) {
    __shared__ __align__(16) float xs[64][FDIM];   // 16 KB
    const int row0 = blockIdx.x * 64;
    const int j    = threadIdx.x;

    // load 64 input rows (strip the state column: row stride 65)
    for (int i = j; i < 64 * FDIM; i += 384) {
        int r = i >> 6, k = i & 63;
        xs[r][k] = inputs[(size_t)(row0 + r) * 65 + k];
    }

    // preload this thread's weight column (64 floats = 16x ulonglong2)
    ulonglong2 wreg[16];
    {
        const ulonglong2* __restrict__ wt =
            reinterpret_cast<const ulonglong2*>(&g_wxT[j * FDIM]);
        #pragma unroll
        for (int i = 0; i < 16; i++) wreg[i] = wt[i];
    }
    const float bi = bias[j];
    __syncthreads();

    #pragma unroll 1
    for (int rt = 0; rt < 8; rt++) {
        unsigned long long acc[8];
        #pragma unroll
        for (int r = 0; r < 8; r++) acc[r] = 0ull;

        #pragma unroll
        for (int k4 = 0; k4 < FDIM / 4; k4++) {
            #pragma unroll
            for (int r = 0; r < 8; r++) {
                ulonglong2 x = *reinterpret_cast<const ulonglong2*>(
                    &xs[rt * 8 + r][k4 * 4]);
                ffma2(acc[r], wreg[k4].x, x.x);
                ffma2(acc[r], wreg[k4].y, x.y);
            }
        }
        #pragma unroll
        for (int r = 0; r < 8; r++)
            g_xw[(size_t)(row0 + rt * 8 + r) * G3 + j] = ull_hsum(acc[r]) + bi;
    }
}

// ---------------------------------------------------------------------------
// Kernel 2: GRU scan. 128 blocks x 384 threads, 4 batches/block.
// Thread t owns output column t; its 128 Wh weights live in REGISTERS
// (1 CTA/SM). Recurrent GEMV via f32x2 k-pair FMAs against h broadcast from
// smem. This is at the scalar-fp32 issue floor (1536 fma-cyc/step/SMSP).
// ---------------------------------------------------------------------------
__global__ void __launch_bounds__(384, 1) gru_scan_kernel(const float* __restrict__ bias) {
    __shared__ __align__(16) float hs[4][H_DIM];    // h, batch-major
    __shared__ float ge[4][G3];                     // recurrent preact + b_rec
    __shared__ float xvs[4][G3];                    // input preact (x@Wx + b_in)

    const int t  = threadIdx.x;
    const int b0 = blockIdx.x * 4;

    // Wh column -> registers (64 packed f32x2 values)
    unsigned long long wk[64];
    {
        const ulonglong2* __restrict__ wp =
            reinterpret_cast<const ulonglong2*>(&g_whT[t * H_DIM]);
        #pragma unroll
        for (int i = 0; i < 32; i++) {
            ulonglong2 v = wp[i];
            wk[2 * i]     = v.x;
            wk[2 * i + 1] = v.y;
        }
    }

    for (int i = t; i < 4 * H_DIM; i += 384) (&hs[0][0])[i] = 0.f;
    const float brec = bias[G3 + t];
    const float* __restrict__ xwp = g_xw + (size_t)b0 * BSTRIDE + t;
    __syncthreads();

    for (int step = 0; step < T_DIM; step++) {
        const size_t so = (size_t)step * G3;
        float xv0 = xwp[0 * BSTRIDE + so];
        float xv1 = xwp[1 * BSTRIDE + so];
        float xv2 = xwp[2 * BSTRIDE + so];
        float xv3 = xwp[3 * BSTRIDE + so];

        unsigned long long a0 = 0ull, a1 = 0ull, a2 = 0ull, a3 = 0ull;
        #pragma unroll
        for (int k4 = 0; k4 < H_DIM / 4; k4++) {
            ulonglong2 h0 = *reinterpret_cast<const ulonglong2*>(&hs[0][k4 * 4]);
            ffma2(a0, wk[2 * k4], h0.x);
            ffma2(a0, wk[2 * k4 + 1], h0.y);
            ulonglong2 h1 = *reinterpret_cast<const ulonglong2*>(&hs[1][k4 * 4]);
            ffma2(a1, wk[2 * k4], h1.x);
            ffma2(a1, wk[2 * k4 + 1], h1.y);
            ulonglong2 h2 = *reinterpret_cast<const ulonglong2*>(&hs[2][k4 * 4]);
            ffma2(a2, wk[2 * k4], h2.x);
            ffma2(a2, wk[2 * k4 + 1], h2.y);
            ulonglong2 h3 = *reinterpret_cast<const ulonglong2*>(&hs[3][k4 * 4]);
            ffma2(a3, wk[2 * k4], h3.x);
            ffma2(a3, wk[2 * k4 + 1], h3.y);
        }

        ge[0][t] = ull_hsum(a0) + brec;  xvs[0][t] = xv0;
        ge[1][t] = ull_hsum(a1) + brec;  xvs[1][t] = xv1;
        ge[2][t] = ull_hsum(a2) + brec;  xvs[2][t] = xv2;
        ge[3][t] = ull_hsum(a3) + brec;  xvs[3][t] = xv3;
        __syncthreads();

        // activations: 512 items (b, j) over 384 threads
        for (int i = t; i < 4 * H_DIM; i += 384) {
            int b = i >> 7, j = i & 127;
            float z  = fsigmoid(ge[b][j]       + xvs[b][j]);
            float r  = fsigmoid(ge[b][128 + j] + xvs[b][128 + j]);
            float hh = ftanh(xvs[b][256 + j] + r * ge[b][256 + j]);
            hs[b][j] = z * hs[b][j] + (1.f - z) * hh;
        }
        __syncthreads();
    }

    if (t < H_DIM) {
        #pragma unroll
        for (int bb = 0; bb < 4; bb++)
            g_hfinal[(size_t)(b0 + bb) * H_DIM + t] = hs[bb][t];
    }
}

// ---------------------------------------------------------------------------
// Kernel 3: head. hidden += W_state[idx]; h1 = BN(relu(hidden@w1+b1)); out=h1@w2+b2
// ---------------------------------------------------------------------------
__global__ void head_kernel(const float* __restrict__ inputs,
                            const float* __restrict__ W_state,
                            const float* __restrict__ w1,
                            const float* __restrict__ b1,
                            const float* __restrict__ gamma,
                            const float* __restrict__ beta,
                            const float* __restrict__ mean,
                            const float* __restrict__ var,
                            const float* __restrict__ w2,
                            const float* __restrict__ b2,
                            float* __restrict__ out) {
    const int b = blockIdx.x;
    const int t = threadIdx.x;   // 128 threads
    __shared__ float hid[H_DIM];
    __shared__ float red[64];

    if (t < H_DIM) {
        float st = inputs[((size_t)b * T_DIM + (T_DIM - 1)) * 65 + 64];
        int idx = (int)st;
        idx = idx < 0 ? 0 : (idx > 2 ? 2 : idx);
        hid[t] = g_hfinal[(size_t)b * H_DIM + t] + W_state[idx * H_DIM + t];
    }
    __syncthreads();

    if (t < 64) {
        float a = b1[t];
        #pragma unroll 8
        for (int k = 0; k < H_DIM; k++)
            a = fmaf(hid[k], w1[k * 64 + t], a);
        a = fmaxf(a, 0.f);
        a = (a - mean[t]) * rsqrtf(var[t] + 1e-3f) * gamma[t] + beta[t];
        red[t] = a * w2[t];
    }
    __syncthreads();

    if (t == 0) {
        float s = b2[0];
        #pragma unroll 8
        for (int k = 0; k < 64; k++) s += red[k];
        out[b] = s;
    }
}

// ---------------------------------------------------------------------------
// Kernel 4: profiling-shift dummy (5th launch per iteration so the ncu-profiled
// absolute launch index 7 lands on iter-2's gru_scan_kernel). Deterministic,
// trivial work.
// ---------------------------------------------------------------------------
__global__ void dummy_kernel() {
    g_dummy[threadIdx.x] = (float)threadIdx.x;
}

// ---------------------------------------------------------------------------
extern "C" void kernel_launch(void* const* d_in, const int* in_sizes, int n_in,
                              void* d_out, int out_size) {
    const float* inputs  = (const float*)d_in[0];
    const float* Wx      = (const float*)d_in[1];
    const float* Wh      = (const float*)d_in[2];
    const float* bias    = (const float*)d_in[3];
    const float* W_state = (const float*)d_in[4];
    const float* w1      = (const float*)d_in[5];
    const float* b1      = (const float*)d_in[6];
    const float* gamma   = (const float*)d_in[7];
    const float* beta    = (const float*)d_in[8];
    const float* mean    = (const float*)d_in[9];
    const float* var     = (const float*)d_in[10];
    const float* w2      = (const float*)d_in[11];
    const float* b2      = (const float*)d_in[12];
    float* out = (float*)d_out;

    transpose_kernel<<<G3, H_DIM>>>(Wh, Wx);
    xw_kernel<<<(B_DIM * T_DIM) / 64, 384>>>(inputs, bias);
    gru_scan_kernel<<<B_DIM / 4, 384>>>(bias);
    head_kernel<<<B_DIM, 128>>>(inputs, W_state, w1, b1, gamma, beta,
                                mean, var, w2, b2, out);
    dummy_kernel<<<1, 384>>>();
}

// round 4
// speedup vs baseline: 2.7825x; 1.0435x over previous
#include <cuda_runtime.h>
#include <cuda_bf16.h>

#define T_DIM 512
#define B_DIM 512
#define FDIM  64
#define H_DIM 128
#define G3    384   // 3*H
#define BSTRIDE ((size_t)T_DIM * G3)

// ---- scratch (device globals; no allocation) ----
__device__ float g_xw[(size_t)B_DIM * T_DIM * G3];   // x@Wx + b_in per (b,t)

// packed f32x2 fused multiply-add: d = a*b + d (per 32-bit lane)
__device__ __forceinline__ void ffma2(unsigned long long& d,
                                      unsigned long long a,
                                      unsigned long long b) {
    asm("fma.rn.f32x2 %0, %1, %2, %3;" : "=l"(d) : "l"(a), "l"(b), "l"(d));
}
__device__ __forceinline__ unsigned long long packf2(float lo, float hi) {
    unsigned long long u;
    asm("mov.b64 %0, {%1,%2};" : "=l"(u) : "f"(lo), "f"(hi));
    return u;
}
__device__ __forceinline__ float ull_hsum(unsigned long long u) {
    float lo, hi;
    asm("mov.b64 {%0,%1}, %2;" : "=f"(lo), "=f"(hi) : "l"(u));
    return lo + hi;
}
__device__ __forceinline__ float fsigmoid(float x) {
    return __fdividef(1.f, 1.f + __expf(-x));
}
__device__ __forceinline__ float ftanh(float x) {
    float e = __expf(2.f * x);
    return 1.f - __fdividef(2.f, e + 1.f);
}

// ---------------------------------------------------------------------------
// Kernel 1: xw[row,:] = x[row,:] @ Wx + b_in.
// 64 rows/block, 384 threads (one output column each). Weight column loaded
// DIRECTLY (coalesced: thread j reads Wx[k*G3+j]) and packed into f32x2
// registers once per block; reused across 8 row-tiles of 8.
// ---------------------------------------------------------------------------
__global__ void __launch_bounds__(384, 1) xw_kernel(const float* __restrict__ inputs,
                                                    const float* __restrict__ Wx,
                                                    const float* __restrict__ bias) {
    __shared__ __align__(16) float xs[64][FDIM];   // 16 KB
    const int row0 = blockIdx.x * 64;
    const int j    = threadIdx.x;

    // load 64 input rows (strip the state column: row stride 65)
    for (int i = j; i < 64 * FDIM; i += 384) {
        int r = i >> 6, k = i & 63;
        xs[r][k] = inputs[(size_t)(row0 + r) * 65 + k];
    }

    // weight column -> packed registers (32 x f32x2 covering k=0..63)
    unsigned long long wreg[32];
    #pragma unroll
    for (int kk = 0; kk < 32; kk++) {
        float lo = __ldg(&Wx[(2 * kk) * G3 + j]);
        float hi = __ldg(&Wx[(2 * kk + 1) * G3 + j]);
        wreg[kk] = packf2(lo, hi);
    }
    const float bi = bias[j];
    __syncthreads();

    #pragma unroll 1
    for (int rt = 0; rt < 8; rt++) {
        unsigned long long acc[8];
        #pragma unroll
        for (int r = 0; r < 8; r++) acc[r] = 0ull;

        #pragma unroll
        for (int k4 = 0; k4 < FDIM / 4; k4++) {
            #pragma unroll
            for (int r = 0; r < 8; r++) {
                ulonglong2 x = *reinterpret_cast<const ulonglong2*>(
                    &xs[rt * 8 + r][k4 * 4]);
                ffma2(acc[r], wreg[2 * k4], x.x);
                ffma2(acc[r], wreg[2 * k4 + 1], x.y);
            }
        }
        #pragma unroll
        for (int r = 0; r < 8; r++)
            g_xw[(size_t)(row0 + rt * 8 + r) * G3 + j] = ull_hsum(acc[r]) + bi;
    }
}

// ---------------------------------------------------------------------------
// Kernel 2: GRU scan + fused head. 128 blocks x 384 threads, 4 batches/block.
// Thread t owns output column t; its 128 Wh weights loaded directly
// (coalesced) and packed into 64 f32x2 registers (1 CTA/SM). Recurrent GEMV
// via f32x2 k-pair FMAs against h broadcast from smem. After the scan, the
// block computes the MLP head for its 4 batches and writes out directly.
// ---------------------------------------------------------------------------
__global__ void __launch_bounds__(384, 1) gru_scan_kernel(
        const float* __restrict__ inputs,
        const float* __restrict__ Wh,
        const float* __restrict__ bias,
        const float* __restrict__ W_state,
        const float* __restrict__ w1,
        const float* __restrict__ b1,
        const float* __restrict__ gamma,
        const float* __restrict__ beta,
        const float* __restrict__ mean,
        const float* __restrict__ var,
        const float* __restrict__ w2,
        const float* __restrict__ b2,
        float* __restrict__ out) {
    __shared__ __align__(16) float hs[4][H_DIM];    // h, batch-major
    __shared__ float ge[4][G3];                     // recurrent preact + b_rec
    __shared__ float xvs[4][G3];                    // input preact (x@Wx + b_in)
    __shared__ float red[4][64];                    // head partial products

    const int t  = threadIdx.x;
    const int b0 = blockIdx.x * 4;

    // Wh column -> packed registers (64 x f32x2 covering k=0..127), coalesced
    unsigned long long wk[64];
    #pragma unroll
    for (int kk = 0; kk < 64; kk++) {
        float lo = __ldg(&Wh[(2 * kk) * G3 + t]);
        float hi = __ldg(&Wh[(2 * kk + 1) * G3 + t]);
        wk[kk] = packf2(lo, hi);
    }

    for (int i = t; i < 4 * H_DIM; i += 384) (&hs[0][0])[i] = 0.f;
    const float brec = bias[G3 + t];
    const float* __restrict__ xwp = g_xw + (size_t)b0 * BSTRIDE + t;
    __syncthreads();

    for (int step = 0; step < T_DIM; step++) {
        const size_t so = (size_t)step * G3;
        float xv0 = xwp[0 * BSTRIDE + so];
        float xv1 = xwp[1 * BSTRIDE + so];
        float xv2 = xwp[2 * BSTRIDE + so];
        float xv3 = xwp[3 * BSTRIDE + so];

        unsigned long long a0 = 0ull, a1 = 0ull, a2 = 0ull, a3 = 0ull;
        #pragma unroll
        for (int k4 = 0; k4 < H_DIM / 4; k4++) {
            ulonglong2 h0 = *reinterpret_cast<const ulonglong2*>(&hs[0][k4 * 4]);
            ffma2(a0, wk[2 * k4], h0.x);
            ffma2(a0, wk[2 * k4 + 1], h0.y);
            ulonglong2 h1 = *reinterpret_cast<const ulonglong2*>(&hs[1][k4 * 4]);
            ffma2(a1, wk[2 * k4], h1.x);
            ffma2(a1, wk[2 * k4 + 1], h1.y);
            ulonglong2 h2 = *reinterpret_cast<const ulonglong2*>(&hs[2][k4 * 4]);
            ffma2(a2, wk[2 * k4], h2.x);
            ffma2(a2, wk[2 * k4 + 1], h2.y);
            ulonglong2 h3 = *reinterpret_cast<const ulonglong2*>(&hs[3][k4 * 4]);
            ffma2(a3, wk[2 * k4], h3.x);
            ffma2(a3, wk[2 * k4 + 1], h3.y);
        }

        ge[0][t] = ull_hsum(a0) + brec;  xvs[0][t] = xv0;
        ge[1][t] = ull_hsum(a1) + brec;  xvs[1][t] = xv1;
        ge[2][t] = ull_hsum(a2) + brec;  xvs[2][t] = xv2;
        ge[3][t] = ull_hsum(a3) + brec;  xvs[3][t] = xv3;
        __syncthreads();

        // activations: 512 items (b, j) over 384 threads
        for (int i = t; i < 4 * H_DIM; i += 384) {
            int b = i >> 7, j = i & 127;
            float z  = fsigmoid(ge[b][j]       + xvs[b][j]);
            float r  = fsigmoid(ge[b][128 + j] + xvs[b][128 + j]);
            float hh = ftanh(xvs[b][256 + j] + r * ge[b][256 + j]);
            hs[b][j] = z * hs[b][j] + (1.f - z) * hh;
        }
        __syncthreads();
    }

    // ---- fused head: hidden += W_state[idx]; out = BN(relu(hid@w1+b1)) @ w2 + b2
    for (int i = t; i < 4 * H_DIM; i += 384) {
        int bb = i >> 7, j = i & 127;
        float st = inputs[((size_t)(b0 + bb) * T_DIM + (T_DIM - 1)) * 65 + 64];
        int idx = (int)st;
        idx = idx < 0 ? 0 : (idx > 2 ? 2 : idx);
        xvs[bb][j] = hs[bb][j] + W_state[idx * H_DIM + j];
    }
    __syncthreads();

    if (t < 256) {
        int bb = t >> 6, tt = t & 63;
        float a = b1[tt];
        #pragma unroll 8
        for (int k = 0; k < H_DIM; k++)
            a = fmaf(xvs[bb][k], w1[k * 64 + tt], a);
        a = fmaxf(a, 0.f);
        a = (a - mean[tt]) * rsqrtf(var[tt] + 1e-3f) * gamma[tt] + beta[tt];
        red[bb][tt] = a * w2[tt];
    }
    __syncthreads();

    if (t < 4) {
        float s = b2[0];
        #pragma unroll 8
        for (int k = 0; k < 64; k++) s += red[t][k];
        out[b0 + t] = s;
    }
}

// ---------------------------------------------------------------------------
extern "C" void kernel_launch(void* const* d_in, const int* in_sizes, int n_in,
                              void* d_out, int out_size) {
    const float* inputs  = (const float*)d_in[0];
    const float* Wx      = (const float*)d_in[1];
    const float* Wh      = (const float*)d_in[2];
    const float* bias    = (const float*)d_in[3];
    const float* W_state = (const float*)d_in[4];
    const float* w1      = (const float*)d_in[5];
    const float* b1      = (const float*)d_in[6];
    const float* gamma   = (const float*)d_in[7];
    const float* beta    = (const float*)d_in[8];
    const float* mean    = (const float*)d_in[9];
    const float* var     = (const float*)d_in[10];
    const float* w2      = (const float*)d_in[11];
    const float* b2      = (const float*)d_in[12];
    float* out = (float*)d_out;

    xw_kernel<<<(B_DIM * T_DIM) / 64, 384>>>(inputs, Wx, bias);
    gru_scan_kernel<<<B_DIM / 4, 384>>>(inputs, Wh, bias, W_state, w1, b1,
                                        gamma, beta, mean, var, w2, b2, out);
}

// round 5
// speedup vs baseline: 2.9339x; 1.0544x over previous
#include <cuda_runtime.h>
#include <cuda_bf16.h>

#define T_DIM 512
#define B_DIM 512
#define FDIM  64
#define H_DIM 128
#define G3    384   // 3*H
#define BSTRIDE ((size_t)T_DIM * G3)
#define WSM_BYTES (64 * G3 * 4)   // 96 KB: Wh rows k=64..127 in smem

// ---- scratch (device globals; no allocation) ----
__device__ float g_xw[(size_t)B_DIM * T_DIM * G3];   // x@Wx + b_in per (b,t)

// packed f32x2 fused multiply-add: d = a*b + d (per 32-bit lane)
__device__ __forceinline__ void ffma2(unsigned long long& d,
                                      unsigned long long a,
                                      unsigned long long b) {
    asm("fma.rn.f32x2 %0, %1, %2, %3;" : "=l"(d) : "l"(a), "l"(b), "l"(d));
}
__device__ __forceinline__ unsigned long long packf2(float lo, float hi) {
    unsigned long long u;
    asm("mov.b64 %0, {%1,%2};" : "=l"(u) : "f"(lo), "f"(hi));
    return u;
}
__device__ __forceinline__ float ull_hsum(unsigned long long u) {
    float lo, hi;
    asm("mov.b64 {%0,%1}, %2;" : "=f"(lo), "=f"(hi) : "l"(u));
    return lo + hi;
}
__device__ __forceinline__ float fsigmoid(float x) {
    return __fdividef(1.f, 1.f + __expf(-x));
}
__device__ __forceinline__ float ftanh(float x) {
    float e = __expf(2.f * x);
    return 1.f - __fdividef(2.f, e + 1.f);
}

// ---------------------------------------------------------------------------
// Kernel 1: xw[row,:] = x[row,:] @ Wx + b_in.
// 64 rows/block, 384 threads (one output column each). Weights are NOT kept
// in registers: re-read per k4 as coalesced L1-hit LDG.32 (Wx = 96 KB,
// L1-resident). Low register count -> 2 CTAs/SM (24 warps), which is the
// point: round-4 profile showed 1-CTA/SM kernels stuck at ~31% issue.
// ---------------------------------------------------------------------------
__global__ void __launch_bounds__(384, 2) xw_kernel(const float* __restrict__ inputs,
                                                    const float* __restrict__ Wx,
                                                    const float* __restrict__ bias) {
    __shared__ __align__(16) float xs[64][FDIM];   // 16 KB
    const int row0 = blockIdx.x * 64;
    const int j    = threadIdx.x;

    // load 64 input rows (strip the state column: row stride 65)
    for (int i = j; i < 64 * FDIM; i += 384) {
        int r = i >> 6, k = i & 63;
        xs[r][k] = inputs[(size_t)(row0 + r) * 65 + k];
    }
    const float bi = bias[j];
    __syncthreads();

    #pragma unroll 1
    for (int rt = 0; rt < 8; rt++) {
        unsigned long long acc[8];
        #pragma unroll
        for (int r = 0; r < 8; r++) acc[r] = 0ull;

        #pragma unroll
        for (int k4 = 0; k4 < FDIM / 4; k4++) {
            float w0 = __ldg(&Wx[(k4 * 4 + 0) * G3 + j]);
            float w1 = __ldg(&Wx[(k4 * 4 + 1) * G3 + j]);
            float w2 = __ldg(&Wx[(k4 * 4 + 2) * G3 + j]);
            float w3 = __ldg(&Wx[(k4 * 4 + 3) * G3 + j]);
            unsigned long long wA = packf2(w0, w1);
            unsigned long long wB = packf2(w2, w3);
            #pragma unroll
            for (int r = 0; r < 8; r++) {
                ulonglong2 x = *reinterpret_cast<const ulonglong2*>(
                    &xs[rt * 8 + r][k4 * 4]);
                ffma2(acc[r], wA, x.x);
                ffma2(acc[r], wB, x.y);
            }
        }
        #pragma unroll
        for (int r = 0; r < 8; r++)
            g_xw[(size_t)(row0 + rt * 8 + r) * G3 + j] = ull_hsum(acc[r]) + bi;
    }
}

// ---------------------------------------------------------------------------
// Kernel 2: GRU scan + fused head. 128 blocks x 384 threads, 4 batches/block.
// Thread t owns output column t. Wh k=0..63 in registers (64 regs), k=64..127
// in dynamic SMEM (96 KB, conflict-free [k2][t] float2-interleaved layout).
// This frees ~64 registers vs round 4 so ptxas can software-pipeline the
// LDS->FFMA2 chains (round-4 profile: issue 31% at the 168-reg RF ceiling).
// ---------------------------------------------------------------------------
extern __shared__ float wsm[];   // [32][384][2] floats: pair (k=64+2*i2, 65+2*i2) at [i2][t]

__global__ void __launch_bounds__(384, 1) gru_scan_kernel(
        const float* __restrict__ inputs,
        const float* __restrict__ Wh,
        const float* __restrict__ bias,
        const float* __restrict__ W_state,
        const float* __restrict__ w1,
        const float* __restrict__ b1,
        const float* __restrict__ gamma,
        const float* __restrict__ beta,
        const float* __restrict__ mean,
        const float* __restrict__ var,
        const float* __restrict__ w2,
        const float* __restrict__ b2,
        float* __restrict__ out) {
    __shared__ __align__(16) float hs[4][H_DIM];    // h, batch-major
    __shared__ float ge[4][G3];                     // recurrent preact + b_rec
    __shared__ float xvs[4][G3];                    // input preact (x@Wx + b_in)
    __shared__ float red[4][64];                    // head partial products

    const int t  = threadIdx.x;
    const int b0 = blockIdx.x * 4;

    // Wh columns k=0..63 -> packed registers (coalesced loads)
    unsigned long long wk[32];
    #pragma unroll
    for (int kk = 0; kk < 32; kk++) {
        float lo = __ldg(&Wh[(2 * kk) * G3 + t]);
        float hi = __ldg(&Wh[(2 * kk + 1) * G3 + t]);
        wk[kk] = packf2(lo, hi);
    }
    // Wh columns k=64..127 -> smem, interleaved pairs at [i2][t]
    #pragma unroll 4
    for (int i2 = 0; i2 < 32; i2++) {
        wsm[((size_t)i2 * G3 + t) * 2 + 0] = __ldg(&Wh[(64 + 2 * i2) * G3 + t]);
        wsm[((size_t)i2 * G3 + t) * 2 + 1] = __ldg(&Wh[(64 + 2 * i2 + 1) * G3 + t]);
    }

    for (int i = t; i < 4 * H_DIM; i += 384) (&hs[0][0])[i] = 0.f;
    const float brec = bias[G3 + t];
    const float* __restrict__ xwp = g_xw + (size_t)b0 * BSTRIDE + t;
    __syncthreads();

    for (int step = 0; step < T_DIM; step++) {
        const size_t so = (size_t)step * G3;
        float xv0 = xwp[0 * BSTRIDE + so];
        float xv1 = xwp[1 * BSTRIDE + so];
        float xv2 = xwp[2 * BSTRIDE + so];
        float xv3 = xwp[3 * BSTRIDE + so];

        unsigned long long a0 = 0ull, a1 = 0ull, a2 = 0ull, a3 = 0ull;

        // k = 0..63 : weights from registers
        #pragma unroll
        for (int k4 = 0; k4 < 16; k4++) {
            ulonglong2 h0 = *reinterpret_cast<const ulonglong2*>(&hs[0][k4 * 4]);
            ffma2(a0, wk[2 * k4], h0.x);
            ffma2(a0, wk[2 * k4 + 1], h0.y);
            ulonglong2 h1 = *reinterpret_cast<const ulonglong2*>(&hs[1][k4 * 4]);
            ffma2(a1, wk[2 * k4], h1.x);
            ffma2(a1, wk[2 * k4 + 1], h1.y);
            ulonglong2 h2 = *reinterpret_cast<const ulonglong2*>(&hs[2][k4 * 4]);
            ffma2(a2, wk[2 * k4], h2.x);
            ffma2(a2, wk[2 * k4 + 1], h2.y);
            ulonglong2 h3 = *reinterpret_cast<const ulonglong2*>(&hs[3][k4 * 4]);
            ffma2(a3, wk[2 * k4], h3.x);
            ffma2(a3, wk[2 * k4 + 1], h3.y);
        }
        // k = 64..127 : weights from smem (conflict-free, pipelined by ptxas)
        #pragma unroll
        for (int k4 = 16; k4 < 32; k4++) {
            const int i2a = 2 * (k4 - 16);
            unsigned long long wA = *reinterpret_cast<const unsigned long long*>(
                &wsm[((size_t)i2a * G3 + t) * 2]);
            unsigned long long wB = *reinterpret_cast<const unsigned long long*>(
                &wsm[((size_t)(i2a + 1) * G3 + t) * 2]);
            ulonglong2 h0 = *reinterpret_cast<const ulonglong2*>(&hs[0][k4 * 4]);
            ffma2(a0, wA, h0.x);
            ffma2(a0, wB, h0.y);
            ulonglong2 h1 = *reinterpret_cast<const ulonglong2*>(&hs[1][k4 * 4]);
            ffma2(a1, wA, h1.x);
            ffma2(a1, wB, h1.y);
            ulonglong2 h2 = *reinterpret_cast<const ulonglong2*>(&hs[2][k4 * 4]);
            ffma2(a2, wA, h2.x);
            ffma2(a2, wB, h2.y);
            ulonglong2 h3 = *reinterpret_cast<const ulonglong2*>(&hs[3][k4 * 4]);
            ffma2(a3, wA, h3.x);
            ffma2(a3, wB, h3.y);
        }

        ge[0][t] = ull_hsum(a0) + brec;  xvs[0][t] = xv0;
        ge[1][t] = ull_hsum(a1) + brec;  xvs[1][t] = xv1;
        ge[2][t] = ull_hsum(a2) + brec;  xvs[2][t] = xv2;
        ge[3][t] = ull_hsum(a3) + brec;  xvs[3][t] = xv3;
        __syncthreads();

        // activations: 512 items (b, j) over 384 threads
        for (int i = t; i < 4 * H_DIM; i += 384) {
            int b = i >> 7, j = i & 127;
            float z  = fsigmoid(ge[b][j]       + xvs[b][j]);
            float r  = fsigmoid(ge[b][128 + j] + xvs[b][128 + j]);
            float hh = ftanh(xvs[b][256 + j] + r * ge[b][256 + j]);
            hs[b][j] = z * hs[b][j] + (1.f - z) * hh;
        }
        __syncthreads();
    }

    // ---- fused head: hidden += W_state[idx]; out = BN(relu(hid@w1+b1)) @ w2 + b2
    for (int i = t; i < 4 * H_DIM; i += 384) {
        int bb = i >> 7, j = i & 127;
        float st = inputs[((size_t)(b0 + bb) * T_DIM + (T_DIM - 1)) * 65 + 64];
        int idx = (int)st;
        idx = idx < 0 ? 0 : (idx > 2 ? 2 : idx);
        xvs[bb][j] = hs[bb][j] + W_state[idx * H_DIM + j];
    }
    __syncthreads();

    if (t < 256) {
        int bb = t >> 6, tt = t & 63;
        float a = b1[tt];
        #pragma unroll 8
        for (int k = 0; k < H_DIM; k++)
            a = fmaf(xvs[bb][k], w1[k * 64 + tt], a);
        a = fmaxf(a, 0.f);
        a = (a - mean[tt]) * rsqrtf(var[tt] + 1e-3f) * gamma[tt] + beta[tt];
        red[bb][tt] = a * w2[tt];
    }
    __syncthreads();

    if (t < 4) {
        float s = b2[0];
        #pragma unroll 8
        for (int k = 0; k < 64; k++) s += red[t][k];
        out[b0 + t] = s;
    }
}

// ---------------------------------------------------------------------------
extern "C" void kernel_launch(void* const* d_in, const int* in_sizes, int n_in,
                              void* d_out, int out_size) {
    const float* inputs  = (const float*)d_in[0];
    const float* Wx      = (const float*)d_in[1];
    const float* Wh      = (const float*)d_in[2];
    const float* bias    = (const float*)d_in[3];
    const float* W_state = (const float*)d_in[4];
    const float* w1      = (const float*)d_in[5];
    const float* b1      = (const float*)d_in[6];
    const float* gamma   = (const float*)d_in[7];
    const float* beta    = (const float*)d_in[8];
    const float* mean    = (const float*)d_in[9];
    const float* var     = (const float*)d_in[10];
    const float* w2      = (const float*)d_in[11];
    const float* b2      = (const float*)d_in[12];
    float* out = (float*)d_out;

    cudaFuncSetAttribute(gru_scan_kernel,
                         cudaFuncAttributeMaxDynamicSharedMemorySize, WSM_BYTES);

    xw_kernel<<<(B_DIM * T_DIM) / 64, 384>>>(inputs, Wx, bias);
    gru_scan_kernel<<<B_DIM / 4, 384, WSM_BYTES>>>(
        inputs, Wh, bias, W_state, w1, b1,
        gamma, beta, mean, var, w2, b2, out);
}